// round 1
// baseline (speedup 1.0000x reference)
#include <cuda_runtime.h>

// ---------------------------------------------------------------------------
// GATv2 layer — algebraically collapsed.
//
// Reference: H = segment_sum(alpha * Vv, dest) with Vv = (V @ Wv.T + b)[dest]
// and alpha a dest-grouped softmax. Since Vv depends only on dest and the sum
// is grouped by dest, H[n] = Vproj[n] * (sum of alpha over segment n) =
// Vproj[n] if node n has any incoming edge, else 0.
// ---------------------------------------------------------------------------

#define D_DIM 128
#define BM 64          // node rows per block
#define BK 32          // k-tile
#define TM 8           // rows per thread
#define TN 4           // cols per thread (cols cg, cg+32, cg+64, cg+96)
#define THREADS 256

#define MAX_NODES 50048

__device__ unsigned char g_has_edge[MAX_NODES];
__device__ int g_is64;

// ---------------------------------------------------------------------------
// Zero the dest-occupancy mask (graph replays must be deterministic).
// ---------------------------------------------------------------------------
__global__ void zero_mask_kernel(int n) {
    int i = blockIdx.x * blockDim.x + threadIdx.x;
    if (i < n) g_has_edge[i] = 0;
}

// ---------------------------------------------------------------------------
// Detect edge_index dtype: for int64 (little-endian) every odd 32-bit word is
// a zero hi-word (values < 50000 << 2^31). For int32 the odd words are src[1],
// src[3], ... — all-zero has probability ~(2e-5)^32. Reads only the first
// 256 bytes, safe for either dtype.
// ---------------------------------------------------------------------------
__global__ void detect_dtype_kernel(const unsigned int* __restrict__ buf) {
    int t = threadIdx.x;                 // 32 threads
    unsigned int v = buf[2 * t + 1];
    unsigned int any = __ballot_sync(0xFFFFFFFFu, v != 0u);
    if (t == 0) g_is64 = (any == 0u) ? 1 : 0;
}

// ---------------------------------------------------------------------------
// Mark nodes that appear as a destination. dest row = edge_index[1] = elements
// [E, 2E) of the flat buffer.
// ---------------------------------------------------------------------------
__global__ void set_mask_kernel(const void* __restrict__ ei, int E) {
    int e = blockIdx.x * blockDim.x + threadIdx.x;
    if (e >= E) return;
    int d;
    if (g_is64) {
        d = (int)((const long long*)ei)[E + e];
    } else {
        d = ((const int*)ei)[E + e];
    }
    g_has_edge[d] = 1;
}

// ---------------------------------------------------------------------------
// H[n,:] = mask[n] * (V[n,:] @ W.T + b)
//
// out[n][o] = sum_k V[n][k] * W[o][k] + b[o]
//
// Block: 64 rows x 128 cols. 256 threads; thread (cg = tid%32, rg = tid/32)
// computes rows 8*rg..8*rg+7, cols {cg, cg+32, cg+64, cg+96}.
// W tile in shared with XOR swizzle (j' = j ^ (row & 7)) so each 8-lane
// LDS.128 subset hits distinct banks. V tile reads are warp-broadcast.
// ---------------------------------------------------------------------------
__global__ __launch_bounds__(THREADS) void vproj_kernel(
    const float* __restrict__ V,
    const float* __restrict__ W,
    const float* __restrict__ b,
    float* __restrict__ out,
    int N)
{
    __shared__ float4 Vs[BM][BK / 4];       // [64][8]  8 KB
    __shared__ float4 Ws[D_DIM][BK / 4];    // [128][8] 16 KB

    const int tid = threadIdx.x;
    const int cg  = tid & 31;               // column group
    const int rg  = tid >> 5;               // row group (0..7)
    const int row0 = blockIdx.x * BM;

    const int lf = tid & 7;                 // float4 index within a row (load)
    const int lr = tid >> 3;                // row index (load), 0..31

    float acc[TM][TN];
    #pragma unroll
    for (int r = 0; r < TM; r++)
        #pragma unroll
        for (int c = 0; c < TN; c++)
            acc[r][c] = 0.0f;

    for (int kt = 0; kt < D_DIM; kt += BK) {
        // ---- load V tile (guarded), plain layout: broadcast-read later ----
        #pragma unroll
        for (int rr = lr; rr < BM; rr += 32) {
            int gr = row0 + rr;
            float4 val = make_float4(0.f, 0.f, 0.f, 0.f);
            if (gr < N)
                val = *(const float4*)&V[(long long)gr * D_DIM + kt + 4 * lf];
            Vs[rr][lf] = val;
        }
        // ---- load W tile, XOR-swizzled ----
        #pragma unroll
        for (int cc = lr; cc < D_DIM; cc += 32) {
            float4 wv = *(const float4*)&W[(long long)cc * D_DIM + kt + 4 * lf];
            Ws[cc][lf ^ (cc & 7)] = wv;
        }
        __syncthreads();

        // ---- compute ----
        #pragma unroll
        for (int kk4 = 0; kk4 < BK / 4; kk4++) {
            float4 w4[TN];
            #pragma unroll
            for (int c = 0; c < TN; c++) {
                int col = cg + 32 * c;                  // (col & 7) == (cg & 7)
                w4[c] = Ws[col][kk4 ^ (cg & 7)];
            }
            #pragma unroll
            for (int r = 0; r < TM; r++) {
                float4 v4 = Vs[TM * rg + r][kk4];       // warp-broadcast
                #pragma unroll
                for (int c = 0; c < TN; c++) {
                    acc[r][c] += v4.x * w4[c].x;
                    acc[r][c] += v4.y * w4[c].y;
                    acc[r][c] += v4.z * w4[c].z;
                    acc[r][c] += v4.w * w4[c].w;
                }
            }
        }
        __syncthreads();
    }

    // ---- epilogue: bias, mask, store ----
    float bias[TN];
    #pragma unroll
    for (int c = 0; c < TN; c++)
        bias[c] = __ldg(&b[cg + 32 * c]);

    #pragma unroll
    for (int r = 0; r < TM; r++) {
        int gr = row0 + TM * rg + r;
        if (gr >= N) continue;
        float fl = (float)g_has_edge[gr];
        #pragma unroll
        for (int c = 0; c < TN; c++) {
            out[(long long)gr * D_DIM + cg + 32 * c] = fl * (acc[r][c] + bias[c]);
        }
    }
}

// ---------------------------------------------------------------------------
// Inputs (metadata order):
//  0: V        [N, 128]  f32
//  1: E        [Ne,128]  f32    (unused — dead after algebraic collapse)
//  2: edge_index [2, Ne] int64/int32
//  3: Wq_w  4: Wq_b  5: Wk_w  6: Wk_b   (unused)
//  7: Wv_w [128,128]  8: Wv_b [128]
//  9: We_w 10: We_b 11: a_w 12: a_b     (unused)
// ---------------------------------------------------------------------------
extern "C" void kernel_launch(void* const* d_in, const int* in_sizes, int n_in,
                              void* d_out, int out_size) {
    const float* V    = (const float*)d_in[0];
    const void*  ei   = d_in[2];
    const float* Wv_w = (const float*)d_in[7];
    const float* Wv_b = (const float*)d_in[8];
    float* out = (float*)d_out;

    int N = in_sizes[0] / D_DIM;
    int E = in_sizes[2] / 2;
    if (N > MAX_NODES) N = MAX_NODES;  // safety; problem is N=50000

    zero_mask_kernel<<<(N + 255) / 256, 256>>>(N);
    detect_dtype_kernel<<<1, 32>>>((const unsigned int*)ei);
    set_mask_kernel<<<(E + 255) / 256, 256>>>(ei, E);
    vproj_kernel<<<(N + BM - 1) / BM, THREADS>>>(V, Wv_w, Wv_b, out, N);
}